// round 10
// baseline (speedup 1.0000x reference)
#include <cuda_runtime.h>
#include <cuda_fp16.h>
#include <mma.h>
#include <cstdint>
#include <cstddef>

using namespace nvcuda;

// Problem constants
#define Tn    2048
#define Bn    4
#define Cn    512
#define Hn    8
#define NREL  33
#define Mrows (Tn*Bn)     // 8192
#define QKVN  (3*Cn)      // 1536

// Scratch
__device__ __half g_xnh[(size_t)Mrows * Cn];
__device__ __half g_qkvh[(size_t)Mrows * QKVN];
__device__ __half g_aoh[(size_t)Mrows * Cn];
__device__ __half g_wqkvh[(size_t)QKVN * Cn];
__device__ __half g_wouth[(size_t)Cn * Cn];

__device__ __forceinline__ uint32_t smem_u32(const void* p) {
    uint32_t a;
    asm("{ .reg .u64 t; cvta.to.shared.u64 t, %1; cvt.u32.u64 %0, t; }" : "=r"(a) : "l"(p));
    return a;
}
#define CP_ASYNC16(dst, src) \
    asm volatile("cp.async.cg.shared.global [%0], [%1], 16;" :: "r"(dst), "l"(src) : "memory")
#define CP_ASYNC4(dst, src) \
    asm volatile("cp.async.ca.shared.global [%0], [%1], 4;" :: "r"(dst), "l"(src) : "memory")
#define CP_COMMIT() asm volatile("cp.async.commit_group;" ::: "memory")
#define CP_WAIT(n)  asm volatile("cp.async.wait_group %0;" :: "n"(n) : "memory")

__device__ __forceinline__ void ldmx4(uint32_t a, uint32_t& r0, uint32_t& r1,
                                      uint32_t& r2, uint32_t& r3) {
    asm volatile("ldmatrix.sync.aligned.m8n8.x4.shared.b16 {%0,%1,%2,%3}, [%4];"
                 : "=r"(r0), "=r"(r1), "=r"(r2), "=r"(r3) : "r"(a));
}
__device__ __forceinline__ void ldmx4t(uint32_t a, uint32_t& r0, uint32_t& r1,
                                       uint32_t& r2, uint32_t& r3) {
    asm volatile("ldmatrix.sync.aligned.m8n8.x4.trans.shared.b16 {%0,%1,%2,%3}, [%4];"
                 : "=r"(r0), "=r"(r1), "=r"(r2), "=r"(r3) : "r"(a));
}
__device__ __forceinline__ void mma16816(float* d, const uint32_t* a,
                                         uint32_t b0, uint32_t b1) {
    asm volatile("mma.sync.aligned.m16n8k16.row.col.f32.f16.f16.f32 "
                 "{%0,%1,%2,%3}, {%4,%5,%6,%7}, {%8,%9}, {%0,%1,%2,%3};"
                 : "+f"(d[0]), "+f"(d[1]), "+f"(d[2]), "+f"(d[3])
                 : "r"(a[0]), "r"(a[1]), "r"(a[2]), "r"(a[3]), "r"(b0), "r"(b1));
}
__device__ __forceinline__ void mma16816h(uint32_t* d, const uint32_t* a,
                                          uint32_t b0, uint32_t b1) {
    asm volatile("mma.sync.aligned.m16n8k16.row.col.f16.f16.f16.f16 "
                 "{%0,%1}, {%2,%3,%4,%5}, {%6,%7}, {%0,%1};"
                 : "+r"(d[0]), "+r"(d[1])
                 : "r"(a[0]), "r"(a[1]), "r"(a[2]), "r"(a[3]), "r"(b0), "r"(b1));
}

// fp32 magic-exp (slow path)
__device__ __forceinline__ float fexp(float s) {
    const float L2E = 1.4426950408889634f;
    const float MAGIC = 12582912.0f;
    float t = fmaf(s, L2E, MAGIC);
    float n = t - MAGIC;
    float f = fmaf(s, L2E, -n);
    float p = 9.6181291076e-3f;
    p = fmaf(p, f, 5.5504108664e-2f);
    p = fmaf(p, f, 2.4022650696e-1f);
    p = fmaf(p, f, 6.9314718056e-1f);
    p = fmaf(p, f, 1.0f);
    return __int_as_float(__float_as_int(p) + (__float_as_int(t) << 23));
}

// half2 SIMD exp
__device__ __forceinline__ uint32_t h2exp_p(__half2 s) {
    const __half2 L2E = __half2half2(__ushort_as_half(0x3DC5));
    const __half2 MAG = __half2half2(__ushort_as_half(0x6600));
    __half2 t = __hfma2(s, L2E, MAG);
    __half2 n = __hsub2(t, MAG);
    __half2 f = __hfma2(s, L2E, __hneg2(n));
    __half2 p = __half2half2(__float2half_rn(5.5504e-2f));
    p = __hfma2(p, f, __half2half2(__float2half_rn(2.40226e-1f)));
    p = __hfma2(p, f, __half2half2(__float2half_rn(6.93147e-1f)));
    p = __hfma2(p, f, __half2half2(__float2half_rn(1.0f)));
    uint32_t tb = *(uint32_t*)&t;
    uint32_t e = ((tb - 0x65F165F1u) << 10) & 0x7C007C00u;
    __half2 r = __hmul2(p, *(__half2*)&e);
    return *(uint32_t*)&r;
}

// ---------------------------------------------------------------------------
__global__ __launch_bounds__(256) void cvt2h(const float* __restrict__ a,
                                             __half* __restrict__ o, int n) {
    int i = (blockIdx.x * 256 + threadIdx.x) * 4;
    if (i < n) {
        float4 v = *(const float4*)(a + i);
        __half2* d = (__half2*)(o + i);
        d[0] = __floats2half2_rn(v.x, v.y);
        d[1] = __floats2half2_rn(v.z, v.w);
    }
}

// ---------------------------------------------------------------------------
__global__ __launch_bounds__(256) void ln_kernel(const float* __restrict__ x,
                                                 const float* __restrict__ gamma,
                                                 const float* __restrict__ beta) {
    int row  = blockIdx.x * blockDim.y + threadIdx.y;
    int lane = threadIdx.x;
    const float* xr = x + (size_t)row * Cn;
    float vals[16];
    float s = 0.f;
#pragma unroll
    for (int i = 0; i < 16; i++) { vals[i] = xr[lane + i * 32]; s += vals[i]; }
#pragma unroll
    for (int o = 16; o; o >>= 1) s += __shfl_xor_sync(0xffffffffu, s, o);
    float mu = s * (1.f / 512.f);
    float v = 0.f;
#pragma unroll
    for (int i = 0; i < 16; i++) { float d = vals[i] - mu; v += d * d; }
#pragma unroll
    for (int o = 16; o; o >>= 1) v += __shfl_xor_sync(0xffffffffu, v, o);
    float inv = rsqrtf(v * (1.f / 512.f) + 1e-5f);
    __half* op = g_xnh + (size_t)row * Cn;
#pragma unroll
    for (int i = 0; i < 16; i++) {
        int c = lane + i * 32;
        op[c] = __float2half_rn((vals[i] - mu) * inv * gamma[c] + beta[c]);
    }
}

// ---------------------------------------------------------------------------
// fp16 WMMA GEMM (unchanged)
// ---------------------------------------------------------------------------
#define HLD 72
#define HBUF_B (128 * HLD * 2)
#define GH_SMEM 73728
#define GE_STAGE_LD 132

__global__ __launch_bounds__(256) void gemm_h(const __half* __restrict__ Wh,
                                              const float* __restrict__ bias,
                                              float* __restrict__ outp,
                                              int N, int mode) {
    extern __shared__ float sm[];
    __half* sh = (__half*)sm;
    uint32_t sb = smem_u32(sm);
    const __half* A = (mode == 1) ? g_xnh : g_aoh;

    const int tid = threadIdx.x, wid = tid >> 5;
    const int m0 = blockIdx.y * 128, n0 = blockIdx.x * 128;
    const int wm = wid & 3, wn = wid >> 2;

    const uint32_t AOFF[2] = {0u, (uint32_t)HBUF_B};
    const uint32_t BOFF[2] = {(uint32_t)(2 * HBUF_B), (uint32_t)(3 * HBUF_B)};

    wmma::fragment<wmma::accumulator, 16, 16, 16, float> acc[2][4];
#pragma unroll
    for (int i = 0; i < 2; i++)
#pragma unroll
        for (int j = 0; j < 4; j++) wmma::fill_fragment(acc[i][j], 0.f);

    auto issue = [&](int c, int bsel) {
        int k0 = c * 64;
#pragma unroll
        for (int t = 0; t < 4; t++) {
            int ch = tid + t * 256;
            int r = ch >> 3, sg = ch & 7;
            CP_ASYNC16(sb + AOFF[bsel] + (uint32_t)(r * HLD + sg * 8) * 2u,
                       A + (size_t)(m0 + r) * 512 + k0 + sg * 8);
            CP_ASYNC16(sb + BOFF[bsel] + (uint32_t)(r * HLD + sg * 8) * 2u,
                       Wh + (size_t)(n0 + r) * 512 + k0 + sg * 8);
        }
        CP_COMMIT();
    };

    issue(0, 0);
    for (int c = 0; c < 8; c++) {
        int bsel = c & 1;
        if (c + 1 < 8) { issue(c + 1, bsel ^ 1); CP_WAIT(1); }
        else           { CP_WAIT(0); }
        __syncthreads();
        const __half* Asb = sh + (AOFF[bsel] >> 1);
        const __half* Bsb = sh + (BOFF[bsel] >> 1);
#pragma unroll
        for (int ks = 0; ks < 4; ks++) {
            wmma::fragment<wmma::matrix_a, 16, 16, 16, __half, wmma::row_major> af[2];
            wmma::fragment<wmma::matrix_b, 16, 16, 16, __half, wmma::col_major> bf[4];
#pragma unroll
            for (int i = 0; i < 2; i++)
                wmma::load_matrix_sync(af[i], Asb + (wm * 32 + i * 16) * HLD + ks * 16, HLD);
#pragma unroll
            for (int j = 0; j < 4; j++)
                wmma::load_matrix_sync(bf[j], Bsb + (wn * 64 + j * 16) * HLD + ks * 16, HLD);
#pragma unroll
            for (int i = 0; i < 2; i++)
#pragma unroll
                for (int j = 0; j < 4; j++)
                    wmma::mma_sync(acc[i][j], af[i], bf[j], acc[i][j]);
        }
        __syncthreads();
    }

    float* stage = sm;
#pragma unroll
    for (int i = 0; i < 2; i++)
#pragma unroll
        for (int j = 0; j < 4; j++)
            wmma::store_matrix_sync(stage + (wm * 32 + i * 16) * GE_STAGE_LD + wn * 64 + j * 16,
                                    acc[i][j], GE_STAGE_LD, wmma::mem_row_major);
    __syncthreads();
#pragma unroll
    for (int it = 0; it < 64; it++) {
        int idx = tid + it * 256;
        int r = idx >> 7, j = idx & 127;
        int n = n0 + j;
        float v = stage[r * GE_STAGE_LD + j] + __ldg(bias + n);
        if (mode == 1) {
            if (n < 512) v *= 0.125f;
            g_qkvh[(size_t)(m0 + r) * QKVN + n] = __float2half_rn(v);
        } else {
            outp[(size_t)(m0 + r) * N + n] = v;
        }
    }
}

// ---------------------------------------------------------------------------
// Flash attention v5: 4 warps x 32 q-rows — K/V fragments reused across
// two m-tiles (halves LDSM traffic). f16-acc S, SIMD softmax, double-buffer.
// ---------------------------------------------------------------------------
#define AK0 0u
#define AV0 9216u
#define AK1 18432u
#define AV1 27648u
#define AM0 36864u
#define AM1 36928u
#define AQR 37120u              // fp32 sqr [128][34]
#define ASQ 54528u              // half Q [128][72]
#define AREL 72960u             // fp32 rel [33][64]
#define ATT_BYTES 81408
#define ATHR 128

__global__ __launch_bounds__(ATHR, 2) void attn_tc(const unsigned char* __restrict__ mask,
                                                   const float* __restrict__ rel_emb) {
    extern __shared__ char smc[];
    const uint32_t sb = smem_u32(smc);
    float* sqr  = (float*)(smc + AQR);
    __half* sQ  = (__half*)(smc + ASQ);
    float* sRel = (float*)(smc + AREL);

    const int tid = threadIdx.x, w = tid >> 5, l = tid & 31;
    const int qb = blockIdx.x, bh = blockIdx.y;
    const int b = bh >> 3, h = bh & 7;
    const int q0 = qb * 128;
    const unsigned char* mrow = mask + b * Tn;

    auto issue = [&](int kb, int bs) {
        int kbase = kb * 64;
#pragma unroll
        for (int i = 0; i < 4; i++) {
            int c = tid + i * ATHR;
            int key = c >> 3, seg = c & 7;
            const __half* gk = g_qkvh + (size_t)((kbase + key) * 4 + b) * QKVN + 512 + h * 64 + seg * 8;
            uint32_t doff = (uint32_t)(key * 72 + seg * 8) * 2u;
            CP_ASYNC16(sb + (bs ? AK1 : AK0) + doff, gk);
            CP_ASYNC16(sb + (bs ? AV1 : AV0) + doff, gk + 512);
        }
        if (tid < 16)
            CP_ASYNC4(sb + (bs ? AM1 : AM0) + tid * 4, mrow + kbase + tid * 4);
        CP_COMMIT();
    };

    issue(0, 0);

#pragma unroll
    for (int i = 0; i < 8; i++) {
        int c = tid + i * ATHR;
        int r = c >> 3, seg = c & 7;
        *(float4*)(sQ + r * 72 + seg * 8) =
            *(const float4*)(g_qkvh + (size_t)((q0 + r) * 4 + b) * QKVN + h * 64 + seg * 8);
    }
    for (int e = tid; e < NREL * 64; e += ATHR) sRel[e] = rel_emb[e];
    __syncthreads();

    for (int e = tid; e < 128 * NREL; e += ATHR) {
        int r = e / NREL, rr = e - r * NREL;
        float a = 0.f;
#pragma unroll
        for (int d = 0; d < 64; d++)
            a = fmaf(__half2float(sQ[r * 72 + d]), sRel[rr * 64 + d], a);
        sqr[r * 34 + rr] = a;
    }

    // Q fragments: 2 m-tiles x 4 k-tiles (warp owns rows w*32 .. w*32+31)
    const int m = l >> 3, r8 = l & 7;
    uint32_t aq[2][4][4];
#pragma unroll
    for (int mt = 0; mt < 2; mt++)
#pragma unroll
        for (int kt = 0; kt < 4; kt++)
            ldmx4(sb + ASQ + (uint32_t)((w * 32 + mt * 16 + (m & 1) * 8 + r8) * 72
                                        + kt * 16 + (m >> 1) * 8) * 2u,
                  aq[mt][kt][0], aq[mt][kt][1], aq[mt][kt][2], aq[mt][kt][3]);
    __syncthreads();

    const int g = l >> 2, qly = l & 3;
    int lr[2][2], rg[2][2];
    float bL[2][2], bH[2][2];
#pragma unroll
    for (int mt = 0; mt < 2; mt++) {
        lr[mt][0] = w * 32 + mt * 16 + g;
        lr[mt][1] = lr[mt][0] + 8;
#pragma unroll
        for (int hh = 0; hh < 2; hh++) {
            rg[mt][hh] = q0 + lr[mt][hh];
            bL[mt][hh] = sqr[lr[mt][hh] * 34 + 0];
            bH[mt][hh] = sqr[lr[mt][hh] * 34 + 32];
        }
    }
    const int qw0 = q0 + w * 32;

    float o[2][8][4];
#pragma unroll
    for (int mt = 0; mt < 2; mt++)
#pragma unroll
        for (int n = 0; n < 8; n++)
#pragma unroll
            for (int e = 0; e < 4; e++) o[mt][n][e] = 0.f;
    float ls[2][2] = {{0.f, 0.f}, {0.f, 0.f}};

    for (int kb = 0; kb < 32; kb++) {
        int bs = kb & 1;
        int kbase = kb * 64;
        if (kb + 1 < 32) { issue(kb + 1, bs ^ 1); CP_WAIT(1); } else { CP_WAIT(0); }
        __syncthreads();
        const uint32_t Kb = sb + (bs ? AK1 : AK0);
        const uint32_t Vb = sb + (bs ? AV1 : AV0);
        const unsigned char* Mb = (const unsigned char*)(smc + (bs ? AM1 : AM0));

        // S = Q @ K^T, fp16 acc; K fragment shared across both m-tiles
        uint32_t shv[2][8][2];
#pragma unroll
        for (int mt = 0; mt < 2; mt++)
#pragma unroll
            for (int n = 0; n < 8; n++) { shv[mt][n][0] = 0u; shv[mt][n][1] = 0u; }
#pragma unroll
        for (int kt = 0; kt < 4; kt++) {
#pragma unroll
            for (int np = 0; np < 4; np++) {
                uint32_t k0, k1, k2, k3;
                ldmx4(Kb + (uint32_t)((np * 16 + (m >> 1) * 8 + r8) * 72
                                      + kt * 16 + (m & 1) * 8) * 2u,
                      k0, k1, k2, k3);
#pragma unroll
                for (int mt = 0; mt < 2; mt++) {
                    mma16816h(shv[mt][2 * np],     aq[mt][kt], k0, k1);
                    mma16816h(shv[mt][2 * np + 1], aq[mt][kt], k2, k3);
                }
            }
        }

        bool lo = (qw0 >= kbase + 79);
        bool hi = (kbase >= qw0 + 47);
        bool fast = lo | hi;
        uint32_t mw = *(const uint32_t*)(Mb + ((l & 15) << 2));
        bool anym = __any_sync(0xffffffffu, mw != 0u);

        if (fast && !anym) {
#pragma unroll
            for (int mt = 0; mt < 2; mt++) {
                __half2 hb0 = __half2half2(__float2half_rn(lo ? bL[mt][0] : bH[mt][0]));
                __half2 hb1 = __half2half2(__float2half_rn(lo ? bL[mt][1] : bH[mt][1]));
                __half2 a0 = __half2half2(__ushort_as_half(0));
                __half2 a1 = a0;
#pragma unroll
                for (int n = 0; n < 8; n++) {
                    shv[mt][n][0] = h2exp_p(__hadd2(*(__half2*)&shv[mt][n][0], hb0));
                    shv[mt][n][1] = h2exp_p(__hadd2(*(__half2*)&shv[mt][n][1], hb1));
                    a0 = __hadd2(a0, *(__half2*)&shv[mt][n][0]);
                    a1 = __hadd2(a1, *(__half2*)&shv[mt][n][1]);
                }
                float2 f0 = __half22float2(a0), f1 = __half22float2(a1);
                ls[mt][0] += f0.x + f0.y;
                ls[mt][1] += f1.x + f1.y;
            }
        } else {
#pragma unroll
            for (int mt = 0; mt < 2; mt++) {
#pragma unroll
                for (int n = 0; n < 8; n++) {
                    int cb = n * 8 + qly * 2;
                    unsigned short mv = *(const unsigned short*)(Mb + cb);
                    float2 v0 = __half22float2(*(__half2*)&shv[mt][n][0]);
                    float2 v1 = __half22float2(*(__half2*)&shv[mt][n][1]);
                    float b00, b01, b10, b11;
                    if (fast) {
                        b00 = b01 = lo ? bL[mt][0] : bH[mt][0];
                        b10 = b11 = lo ? bL[mt][1] : bH[mt][1];
                    } else {
                        int c = kbase + cb;
                        int rA = min(max(c - rg[mt][0], -16), 16);
                        int rB = min(max(c + 1 - rg[mt][0], -16), 16);
                        int rC = min(max(c - rg[mt][1], -16), 16);
                        int rD = min(max(c + 1 - rg[mt][1], -16), 16);
                        b00 = sqr[lr[mt][0] * 34 + rA + 16];
                        b01 = sqr[lr[mt][0] * 34 + rB + 16];
                        b10 = sqr[lr[mt][1] * 34 + rC + 16];
                        b11 = sqr[lr[mt][1] * 34 + rD + 16];
                    }
                    float p00 = (mv & 0xff) ? 0.f : fexp(v0.x + b00);
                    float p01 = (mv >> 8)   ? 0.f : fexp(v0.y + b01);
                    float p10 = (mv & 0xff) ? 0.f : fexp(v1.x + b10);
                    float p11 = (mv >> 8)   ? 0.f : fexp(v1.y + b11);
                    ls[mt][0] += p00 + p01;
                    ls[mt][1] += p10 + p11;
                    __half2 h0 = __floats2half2_rn(p00, p01);
                    __half2 h1 = __floats2half2_rn(p10, p11);
                    shv[mt][n][0] = *(uint32_t*)&h0;
                    shv[mt][n][1] = *(uint32_t*)&h1;
                }
            }
        }

        // O += P @ V; V fragments shared across m-tiles
#pragma unroll
        for (int kt = 0; kt < 4; kt++) {
            uint32_t pf0[4] = {shv[0][2 * kt][0], shv[0][2 * kt][1],
                               shv[0][2 * kt + 1][0], shv[0][2 * kt + 1][1]};
            uint32_t pf1[4] = {shv[1][2 * kt][0], shv[1][2 * kt][1],
                               shv[1][2 * kt + 1][0], shv[1][2 * kt + 1][1]};
#pragma unroll
            for (int ndp = 0; ndp < 4; ndp++) {
                uint32_t v0, v1, v2, v3;
                ldmx4t(Vb + (uint32_t)((kt * 16 + (m & 1) * 8 + r8) * 72
                                       + ndp * 16 + (m >> 1) * 8) * 2u,
                       v0, v1, v2, v3);
                mma16816(o[0][2 * ndp],     pf0, v0, v1);
                mma16816(o[0][2 * ndp + 1], pf0, v2, v3);
                mma16816(o[1][2 * ndp],     pf1, v0, v1);
                mma16816(o[1][2 * ndp + 1], pf1, v2, v3);
            }
        }
        __syncthreads();
    }

    // final reduce + normalize + store
#pragma unroll
    for (int mt = 0; mt < 2; mt++) {
        float s0 = ls[mt][0], s1 = ls[mt][1];
        s0 += __shfl_xor_sync(0xffffffffu, s0, 1);
        s0 += __shfl_xor_sync(0xffffffffu, s0, 2);
        s1 += __shfl_xor_sync(0xffffffffu, s1, 1);
        s1 += __shfl_xor_sync(0xffffffffu, s1, 2);
        float inv0 = 1.f / s0, inv1 = 1.f / s1;
#pragma unroll
        for (int n = 0; n < 8; n++) {
            int col = h * 64 + n * 8 + qly * 2;
            *(__half2*)(g_aoh + (size_t)(rg[mt][0] * 4 + b) * Cn + col) =
                __floats2half2_rn(o[mt][n][0] * inv0, o[mt][n][1] * inv0);
            *(__half2*)(g_aoh + (size_t)(rg[mt][1] * 4 + b) * Cn + col) =
                __floats2half2_rn(o[mt][n][2] * inv1, o[mt][n][3] * inv1);
        }
    }
}

// ---------------------------------------------------------------------------
extern "C" void kernel_launch(void* const* d_in, const int* in_sizes, int n_in,
                              void* d_out, int out_size) {
    const float* x            = (const float*)d_in[0];
    const unsigned char* mask = (const unsigned char*)d_in[1];
    const float* ln_g         = (const float*)d_in[2];
    const float* ln_b         = (const float*)d_in[3];
    const float* w_qkv        = (const float*)d_in[4];
    const float* b_qkv        = (const float*)d_in[5];
    const float* w_out        = (const float*)d_in[6];
    const float* b_out        = (const float*)d_in[7];
    const float* rel_emb      = (const float*)d_in[8];
    float* out                = (float*)d_out;

    cudaFuncSetAttribute(gemm_h, cudaFuncAttributeMaxDynamicSharedMemorySize, GH_SMEM);
    cudaFuncSetAttribute(attn_tc, cudaFuncAttributeMaxDynamicSharedMemorySize, ATT_BYTES);

    __half* wq_h; cudaGetSymbolAddress((void**)&wq_h, g_wqkvh);
    __half* wo_h; cudaGetSymbolAddress((void**)&wo_h, g_wouth);

    cvt2h<<<(QKVN * Cn / 4 + 255) / 256, 256>>>(w_qkv, wq_h, QKVN * Cn);
    cvt2h<<<(Cn * Cn / 4 + 255) / 256, 256>>>(w_out, wo_h, Cn * Cn);
    ln_kernel<<<Mrows / 8, dim3(32, 8)>>>(x, ln_g, ln_b);
    gemm_h<<<dim3(QKVN / 128, Mrows / 128), 256, GH_SMEM>>>(wq_h, b_qkv, nullptr, QKVN, 1);
    attn_tc<<<dim3(Tn / 128, Bn * Hn), ATHR, ATT_BYTES>>>(mask, rel_emb);
    gemm_h<<<dim3(Cn / 128, Mrows / 128), 256, GH_SMEM>>>(wo_h, b_out, out, Cn, 0);
}

// round 11
// speedup vs baseline: 1.0189x; 1.0189x over previous
#include <cuda_runtime.h>
#include <cuda_fp16.h>
#include <mma.h>
#include <cstdint>
#include <cstddef>

using namespace nvcuda;

// Problem constants
#define Tn    2048
#define Bn    4
#define Cn    512
#define Hn    8
#define NREL  33
#define Mrows (Tn*Bn)     // 8192
#define QKVN  (3*Cn)      // 1536

// Scratch
__device__ __half g_xnh[(size_t)Mrows * Cn];
__device__ __half g_qkvh[(size_t)Mrows * QKVN];
__device__ __half g_aoh[(size_t)Mrows * Cn];
__device__ __half g_wqkvh[(size_t)QKVN * Cn];
__device__ __half g_wouth[(size_t)Cn * Cn];

__device__ __forceinline__ uint32_t smem_u32(const void* p) {
    uint32_t a;
    asm("{ .reg .u64 t; cvta.to.shared.u64 t, %1; cvt.u32.u64 %0, t; }" : "=r"(a) : "l"(p));
    return a;
}
#define CP_ASYNC16(dst, src) \
    asm volatile("cp.async.cg.shared.global [%0], [%1], 16;" :: "r"(dst), "l"(src) : "memory")
#define CP_ASYNC4(dst, src) \
    asm volatile("cp.async.ca.shared.global [%0], [%1], 4;" :: "r"(dst), "l"(src) : "memory")
#define CP_COMMIT() asm volatile("cp.async.commit_group;" ::: "memory")
#define CP_WAIT(n)  asm volatile("cp.async.wait_group %0;" :: "n"(n) : "memory")

__device__ __forceinline__ void ldmx4(uint32_t a, uint32_t& r0, uint32_t& r1,
                                      uint32_t& r2, uint32_t& r3) {
    asm volatile("ldmatrix.sync.aligned.m8n8.x4.shared.b16 {%0,%1,%2,%3}, [%4];"
                 : "=r"(r0), "=r"(r1), "=r"(r2), "=r"(r3) : "r"(a));
}
__device__ __forceinline__ void ldmx4t(uint32_t a, uint32_t& r0, uint32_t& r1,
                                       uint32_t& r2, uint32_t& r3) {
    asm volatile("ldmatrix.sync.aligned.m8n8.x4.trans.shared.b16 {%0,%1,%2,%3}, [%4];"
                 : "=r"(r0), "=r"(r1), "=r"(r2), "=r"(r3) : "r"(a));
}
__device__ __forceinline__ void mma16816(float* d, const uint32_t* a,
                                         uint32_t b0, uint32_t b1) {
    asm volatile("mma.sync.aligned.m16n8k16.row.col.f32.f16.f16.f32 "
                 "{%0,%1,%2,%3}, {%4,%5,%6,%7}, {%8,%9}, {%0,%1,%2,%3};"
                 : "+f"(d[0]), "+f"(d[1]), "+f"(d[2]), "+f"(d[3])
                 : "r"(a[0]), "r"(a[1]), "r"(a[2]), "r"(a[3]), "r"(b0), "r"(b1));
}
__device__ __forceinline__ void mma16816h(uint32_t* d, const uint32_t* a,
                                          uint32_t b0, uint32_t b1) {
    asm volatile("mma.sync.aligned.m16n8k16.row.col.f16.f16.f16.f16 "
                 "{%0,%1}, {%2,%3,%4,%5}, {%6,%7}, {%0,%1};"
                 : "+r"(d[0]), "+r"(d[1])
                 : "r"(a[0]), "r"(a[1]), "r"(a[2]), "r"(a[3]), "r"(b0), "r"(b1));
}

// fp32 magic-exp (slow path)
__device__ __forceinline__ float fexp(float s) {
    const float L2E = 1.4426950408889634f;
    const float MAGIC = 12582912.0f;
    float t = fmaf(s, L2E, MAGIC);
    float n = t - MAGIC;
    float f = fmaf(s, L2E, -n);
    float p = 9.6181291076e-3f;
    p = fmaf(p, f, 5.5504108664e-2f);
    p = fmaf(p, f, 2.4022650696e-1f);
    p = fmaf(p, f, 6.9314718056e-1f);
    p = fmaf(p, f, 1.0f);
    return __int_as_float(__float_as_int(p) + (__float_as_int(t) << 23));
}

// half2 SIMD exp
__device__ __forceinline__ uint32_t h2exp_p(__half2 s) {
    const __half2 L2E = __half2half2(__ushort_as_half(0x3DC5));
    const __half2 MAG = __half2half2(__ushort_as_half(0x6600));
    __half2 t = __hfma2(s, L2E, MAG);
    __half2 n = __hsub2(t, MAG);
    __half2 f = __hfma2(s, L2E, __hneg2(n));
    __half2 p = __half2half2(__float2half_rn(5.5504e-2f));
    p = __hfma2(p, f, __half2half2(__float2half_rn(2.40226e-1f)));
    p = __hfma2(p, f, __half2half2(__float2half_rn(6.93147e-1f)));
    p = __hfma2(p, f, __half2half2(__float2half_rn(1.0f)));
    uint32_t tb = *(uint32_t*)&t;
    uint32_t e = ((tb - 0x65F165F1u) << 10) & 0x7C007C00u;
    __half2 r = __hmul2(p, *(__half2*)&e);
    return *(uint32_t*)&r;
}

// ---------------------------------------------------------------------------
__global__ __launch_bounds__(256) void cvt2h(const float* __restrict__ a,
                                             __half* __restrict__ o, int n) {
    int i = (blockIdx.x * 256 + threadIdx.x) * 4;
    if (i < n) {
        float4 v = *(const float4*)(a + i);
        __half2* d = (__half2*)(o + i);
        d[0] = __floats2half2_rn(v.x, v.y);
        d[1] = __floats2half2_rn(v.z, v.w);
    }
}

// ---------------------------------------------------------------------------
__global__ __launch_bounds__(256) void ln_kernel(const float* __restrict__ x,
                                                 const float* __restrict__ gamma,
                                                 const float* __restrict__ beta) {
    int row  = blockIdx.x * blockDim.y + threadIdx.y;
    int lane = threadIdx.x;
    const float* xr = x + (size_t)row * Cn;
    float vals[16];
    float s = 0.f;
#pragma unroll
    for (int i = 0; i < 16; i++) { vals[i] = xr[lane + i * 32]; s += vals[i]; }
#pragma unroll
    for (int o = 16; o; o >>= 1) s += __shfl_xor_sync(0xffffffffu, s, o);
    float mu = s * (1.f / 512.f);
    float v = 0.f;
#pragma unroll
    for (int i = 0; i < 16; i++) { float d = vals[i] - mu; v += d * d; }
#pragma unroll
    for (int o = 16; o; o >>= 1) v += __shfl_xor_sync(0xffffffffu, v, o);
    float inv = rsqrtf(v * (1.f / 512.f) + 1e-5f);
    __half* op = g_xnh + (size_t)row * Cn;
#pragma unroll
    for (int i = 0; i < 16; i++) {
        int c = lane + i * 32;
        op[c] = __float2half_rn((vals[i] - mu) * inv * gamma[c] + beta[c]);
    }
}

// ---------------------------------------------------------------------------
// fp16 WMMA GEMM (unchanged)
// ---------------------------------------------------------------------------
#define HLD 72
#define HBUF_B (128 * HLD * 2)
#define GH_SMEM 73728
#define GE_STAGE_LD 132

__global__ __launch_bounds__(256) void gemm_h(const __half* __restrict__ Wh,
                                              const float* __restrict__ bias,
                                              float* __restrict__ outp,
                                              int N, int mode) {
    extern __shared__ float sm[];
    __half* sh = (__half*)sm;
    uint32_t sb = smem_u32(sm);
    const __half* A = (mode == 1) ? g_xnh : g_aoh;

    const int tid = threadIdx.x, wid = tid >> 5;
    const int m0 = blockIdx.y * 128, n0 = blockIdx.x * 128;
    const int wm = wid & 3, wn = wid >> 2;

    const uint32_t AOFF[2] = {0u, (uint32_t)HBUF_B};
    const uint32_t BOFF[2] = {(uint32_t)(2 * HBUF_B), (uint32_t)(3 * HBUF_B)};

    wmma::fragment<wmma::accumulator, 16, 16, 16, float> acc[2][4];
#pragma unroll
    for (int i = 0; i < 2; i++)
#pragma unroll
        for (int j = 0; j < 4; j++) wmma::fill_fragment(acc[i][j], 0.f);

    auto issue = [&](int c, int bsel) {
        int k0 = c * 64;
#pragma unroll
        for (int t = 0; t < 4; t++) {
            int ch = tid + t * 256;
            int r = ch >> 3, sg = ch & 7;
            CP_ASYNC16(sb + AOFF[bsel] + (uint32_t)(r * HLD + sg * 8) * 2u,
                       A + (size_t)(m0 + r) * 512 + k0 + sg * 8);
            CP_ASYNC16(sb + BOFF[bsel] + (uint32_t)(r * HLD + sg * 8) * 2u,
                       Wh + (size_t)(n0 + r) * 512 + k0 + sg * 8);
        }
        CP_COMMIT();
    };

    issue(0, 0);
    for (int c = 0; c < 8; c++) {
        int bsel = c & 1;
        if (c + 1 < 8) { issue(c + 1, bsel ^ 1); CP_WAIT(1); }
        else           { CP_WAIT(0); }
        __syncthreads();
        const __half* Asb = sh + (AOFF[bsel] >> 1);
        const __half* Bsb = sh + (BOFF[bsel] >> 1);
#pragma unroll
        for (int ks = 0; ks < 4; ks++) {
            wmma::fragment<wmma::matrix_a, 16, 16, 16, __half, wmma::row_major> af[2];
            wmma::fragment<wmma::matrix_b, 16, 16, 16, __half, wmma::col_major> bf[4];
#pragma unroll
            for (int i = 0; i < 2; i++)
                wmma::load_matrix_sync(af[i], Asb + (wm * 32 + i * 16) * HLD + ks * 16, HLD);
#pragma unroll
            for (int j = 0; j < 4; j++)
                wmma::load_matrix_sync(bf[j], Bsb + (wn * 64 + j * 16) * HLD + ks * 16, HLD);
#pragma unroll
            for (int i = 0; i < 2; i++)
#pragma unroll
                for (int j = 0; j < 4; j++)
                    wmma::mma_sync(acc[i][j], af[i], bf[j], acc[i][j]);
        }
        __syncthreads();
    }

    float* stage = sm;
#pragma unroll
    for (int i = 0; i < 2; i++)
#pragma unroll
        for (int j = 0; j < 4; j++)
            wmma::store_matrix_sync(stage + (wm * 32 + i * 16) * GE_STAGE_LD + wn * 64 + j * 16,
                                    acc[i][j], GE_STAGE_LD, wmma::mem_row_major);
    __syncthreads();
#pragma unroll
    for (int it = 0; it < 64; it++) {
        int idx = tid + it * 256;
        int r = idx >> 7, j = idx & 127;
        int n = n0 + j;
        float v = stage[r * GE_STAGE_LD + j] + __ldg(bias + n);
        if (mode == 1) {
            if (n < 512) v *= 0.125f;
            g_qkvh[(size_t)(m0 + r) * QKVN + n] = __float2half_rn(v);
        } else {
            outp[(size_t)(m0 + r) * N + n] = v;
        }
    }
}

// ---------------------------------------------------------------------------
// Flash attention v6: round-9 layout (8 warps x 16 rows) + 3-stage cp.async
// ring + ONE barrier per tile (wait -> sync -> issue(kb+2) -> compute).
// ---------------------------------------------------------------------------
#define ASTG  18432u            // per-stage K(9216)+V(9216)
#define AMASK 55296u            // 3 x 64B mask slots (padded)
#define AQR   55552u            // fp32 sqr [128][34] = 17408
#define ASQ   72960u            // half Q [128][72]   = 18432
#define AREL  91392u            // fp32 rel [33][64]  = 8448
#define ATT_BYTES 99840

__global__ __launch_bounds__(256, 2) void attn_tc(const unsigned char* __restrict__ mask,
                                                  const float* __restrict__ rel_emb) {
    extern __shared__ char smc[];
    const uint32_t sb = smem_u32(smc);
    float* sqr  = (float*)(smc + AQR);
    __half* sQ  = (__half*)(smc + ASQ);
    float* sRel = (float*)(smc + AREL);

    const int tid = threadIdx.x, w = tid >> 5, l = tid & 31;
    const int qb = blockIdx.x, bh = blockIdx.y;
    const int b = bh >> 3, h = bh & 7;
    const int q0 = qb * 128;
    const unsigned char* mrow = mask + b * Tn;

    auto issue = [&](int kb) {
        int st = kb % 3;
        int kbase = kb * 64;
#pragma unroll
        for (int i = 0; i < 2; i++) {
            int c = tid + i * 256;
            int key = c >> 3, seg = c & 7;
            const __half* gk = g_qkvh + (size_t)((kbase + key) * 4 + b) * QKVN + 512 + h * 64 + seg * 8;
            uint32_t doff = (uint32_t)(key * 72 + seg * 8) * 2u;
            CP_ASYNC16(sb + st * ASTG + doff, gk);
            CP_ASYNC16(sb + st * ASTG + 9216u + doff, gk + 512);
        }
        if (tid < 16)
            CP_ASYNC4(sb + AMASK + st * 64 + tid * 4, mrow + kbase + tid * 4);
        CP_COMMIT();
    };

    issue(0);
    issue(1);

    // Stage Q and rel_emb
#pragma unroll
    for (int i = 0; i < 4; i++) {
        int c = tid + i * 256;
        int r = c >> 3, seg = c & 7;
        *(float4*)(sQ + r * 72 + seg * 8) =
            *(const float4*)(g_qkvh + (size_t)((q0 + r) * 4 + b) * QKVN + h * 64 + seg * 8);
    }
    for (int e = tid; e < NREL * 64; e += 256) sRel[e] = rel_emb[e];
    __syncthreads();

    for (int e = tid; e < 128 * NREL; e += 256) {
        int r = e / NREL, rr = e - r * NREL;
        float a = 0.f;
#pragma unroll
        for (int d = 0; d < 64; d++)
            a = fmaf(__half2float(sQ[r * 72 + d]), sRel[rr * 64 + d], a);
        sqr[r * 34 + rr] = a;
    }

    const int m = l >> 3, r8 = l & 7;
    uint32_t aq[4][4];
#pragma unroll
    for (int kt = 0; kt < 4; kt++)
        ldmx4(sb + ASQ + (uint32_t)((w * 16 + (m & 1) * 8 + r8) * 72 + kt * 16 + (m >> 1) * 8) * 2u,
              aq[kt][0], aq[kt][1], aq[kt][2], aq[kt][3]);
    __syncthreads();

    const int g = l >> 2, qly = l & 3;
    const int lr0 = w * 16 + g, lr1 = lr0 + 8;
    const int rg0 = q0 + lr0, rg1 = q0 + lr1;
    const int qw0 = q0 + w * 16;
    const float bl0 = sqr[lr0 * 34 + 0],  bl1 = sqr[lr1 * 34 + 0];
    const float bh0 = sqr[lr0 * 34 + 32], bh1 = sqr[lr1 * 34 + 32];

    float o[8][4];
#pragma unroll
    for (int n = 0; n < 8; n++)
#pragma unroll
        for (int e = 0; e < 4; e++) o[n][e] = 0.f;
    float l0 = 0.f, l1 = 0.f;

    for (int kb = 0; kb < 32; kb++) {
        int st = kb % 3;
        int kbase = kb * 64;
        if (kb < 31) { CP_WAIT(1); } else { CP_WAIT(0); }
        __syncthreads();              // stage kb visible to all; iter kb-1 compute done
        if (kb + 2 < 32) issue(kb + 2);   // overwrites stage (kb-1)%3 — safe post-sync

        const uint32_t Kb = sb + st * ASTG;
        const uint32_t Vb = Kb + 9216u;
        const unsigned char* Mb = (const unsigned char*)(smc + AMASK + st * 64);

        // S = Q @ K^T, fp16 accumulators
        uint32_t shv[8][2];
#pragma unroll
        for (int n = 0; n < 8; n++) { shv[n][0] = 0u; shv[n][1] = 0u; }
#pragma unroll
        for (int kt = 0; kt < 4; kt++) {
#pragma unroll
            for (int np = 0; np < 4; np++) {
                uint32_t k0, k1, k2, k3;
                ldmx4(Kb + (uint32_t)((np * 16 + (m >> 1) * 8 + r8) * 72 + kt * 16 + (m & 1) * 8) * 2u,
                      k0, k1, k2, k3);
                mma16816h(shv[2 * np],     aq[kt], k0, k1);
                mma16816h(shv[2 * np + 1], aq[kt], k2, k3);
            }
        }

        bool lo = (qw0 >= kbase + 79);
        bool hi = (kbase >= qw0 + 31);
        bool fast = lo | hi;
        uint32_t mw = *(const uint32_t*)(Mb + ((l & 15) << 2));
        bool anym = __any_sync(0xffffffffu, mw != 0u);

        if (fast && !anym) {
            __half2 hb0 = __half2half2(__float2half_rn(lo ? bl0 : bh0));
            __half2 hb1 = __half2half2(__float2half_rn(lo ? bl1 : bh1));
            __half2 a0 = __half2half2(__ushort_as_half(0));
            __half2 a1 = a0;
#pragma unroll
            for (int n = 0; n < 8; n++) {
                shv[n][0] = h2exp_p(__hadd2(*(__half2*)&shv[n][0], hb0));
                shv[n][1] = h2exp_p(__hadd2(*(__half2*)&shv[n][1], hb1));
                a0 = __hadd2(a0, *(__half2*)&shv[n][0]);
                a1 = __hadd2(a1, *(__half2*)&shv[n][1]);
            }
            float2 f0 = __half22float2(a0), f1 = __half22float2(a1);
            l0 += f0.x + f0.y;
            l1 += f1.x + f1.y;
        } else {
#pragma unroll
            for (int n = 0; n < 8; n++) {
                int cb = n * 8 + qly * 2;
                unsigned short mv = *(const unsigned short*)(Mb + cb);
                float2 v0 = __half22float2(*(__half2*)&shv[n][0]);
                float2 v1 = __half22float2(*(__half2*)&shv[n][1]);
                float b00, b01, b10, b11;
                if (fast) { b00 = b01 = lo ? bl0 : bh0; b10 = b11 = lo ? bl1 : bh1; }
                else {
                    int c = kbase + cb;
                    int rA = min(max(c - rg0, -16), 16), rB = min(max(c + 1 - rg0, -16), 16);
                    int rC = min(max(c - rg1, -16), 16), rD = min(max(c + 1 - rg1, -16), 16);
                    b00 = sqr[lr0 * 34 + rA + 16]; b01 = sqr[lr0 * 34 + rB + 16];
                    b10 = sqr[lr1 * 34 + rC + 16]; b11 = sqr[lr1 * 34 + rD + 16];
                }
                float p00 = (mv & 0xff) ? 0.f : fexp(v0.x + b00);
                float p01 = (mv >> 8)   ? 0.f : fexp(v0.y + b01);
                float p10 = (mv & 0xff) ? 0.f : fexp(v1.x + b10);
                float p11 = (mv >> 8)   ? 0.f : fexp(v1.y + b11);
                l0 += p00 + p01;
                l1 += p10 + p11;
                __half2 h0 = __floats2half2_rn(p00, p01);
                __half2 h1 = __floats2half2_rn(p10, p11);
                shv[n][0] = *(uint32_t*)&h0;
                shv[n][1] = *(uint32_t*)&h1;
            }
        }

        // O += P @ V
#pragma unroll
        for (int kt = 0; kt < 4; kt++) {
            uint32_t pf[4] = {shv[2 * kt][0], shv[2 * kt][1],
                              shv[2 * kt + 1][0], shv[2 * kt + 1][1]};
#pragma unroll
            for (int ndp = 0; ndp < 4; ndp++) {
                uint32_t v0, v1, v2, v3;
                ldmx4t(Vb + (uint32_t)((kt * 16 + (m & 1) * 8 + r8) * 72 + ndp * 16 + (m >> 1) * 8) * 2u,
                       v0, v1, v2, v3);
                mma16816(o[2 * ndp],     pf, v0, v1);
                mma16816(o[2 * ndp + 1], pf, v2, v3);
            }
        }
        // no trailing barrier: 3-stage ring + next iteration's barrier cover reuse
    }

    l0 += __shfl_xor_sync(0xffffffffu, l0, 1);
    l0 += __shfl_xor_sync(0xffffffffu, l0, 2);
    l1 += __shfl_xor_sync(0xffffffffu, l1, 1);
    l1 += __shfl_xor_sync(0xffffffffu, l1, 2);
    float inv0 = 1.f / l0, inv1 = 1.f / l1;
#pragma unroll
    for (int n = 0; n < 8; n++) {
        int col = h * 64 + n * 8 + qly * 2;
        *(__half2*)(g_aoh + (size_t)(rg0 * 4 + b) * Cn + col) =
            __floats2half2_rn(o[n][0] * inv0, o[n][1] * inv0);
        *(__half2*)(g_aoh + (size_t)(rg1 * 4 + b) * Cn + col) =
            __floats2half2_rn(o[n][2] * inv1, o[n][3] * inv1);
    }
}

// ---------------------------------------------------------------------------
extern "C" void kernel_launch(void* const* d_in, const int* in_sizes, int n_in,
                              void* d_out, int out_size) {
    const float* x            = (const float*)d_in[0];
    const unsigned char* mask = (const unsigned char*)d_in[1];
    const float* ln_g         = (const float*)d_in[2];
    const float* ln_b         = (const float*)d_in[3];
    const float* w_qkv        = (const float*)d_in[4];
    const float* b_qkv        = (const float*)d_in[5];
    const float* w_out        = (const float*)d_in[6];
    const float* b_out        = (const float*)d_in[7];
    const float* rel_emb      = (const float*)d_in[8];
    float* out                = (float*)d_out;

    cudaFuncSetAttribute(gemm_h, cudaFuncAttributeMaxDynamicSharedMemorySize, GH_SMEM);
    cudaFuncSetAttribute(attn_tc, cudaFuncAttributeMaxDynamicSharedMemorySize, ATT_BYTES);

    __half* wq_h; cudaGetSymbolAddress((void**)&wq_h, g_wqkvh);
    __half* wo_h; cudaGetSymbolAddress((void**)&wo_h, g_wouth);

    cvt2h<<<(QKVN * Cn / 4 + 255) / 256, 256>>>(w_qkv, wq_h, QKVN * Cn);
    cvt2h<<<(Cn * Cn / 4 + 255) / 256, 256>>>(w_out, wo_h, Cn * Cn);
    ln_kernel<<<Mrows / 8, dim3(32, 8)>>>(x, ln_g, ln_b);
    gemm_h<<<dim3(QKVN / 128, Mrows / 128), 256, GH_SMEM>>>(wq_h, b_qkv, nullptr, QKVN, 1);
    attn_tc<<<dim3(Tn / 128, Bn * Hn), 256, ATT_BYTES>>>(mask, rel_emb);
    gemm_h<<<dim3(Cn / 128, Mrows / 128), 256, GH_SMEM>>>(wo_h, b_out, out, Cn, 0);
}